// round 3
// baseline (speedup 1.0000x reference)
#include <cuda_runtime.h>

// SimpleSNN: T=500 sequential steps, B=2048, 12 -> 38 (RLeaky) -> 7 (Leaky)
// Outputs flat: spk1[T,B,38], mem1[T,B,38], spk2[T,B,7], mem2[T,B,7]

#define T_STEPS  500
#define BATCH    2048
#define NIN      12
#define NL1      38
#define NL2      7
#define NB       4              // batch elements per block
#define NTHREADS 192
#define L1_THREADS (NB*NL1)     // 152
#define L2_BASE    160          // layer-2 threads start at a warp boundary
#define L2_THREADS (NB*NL2)     // 28
#define X_THREADS  (NB*NIN)     // 48
#define W2STRIDE   44           // pad W2 rows: 44*4B=176B -> distinct bank groups per k

__global__ __launch_bounds__(NTHREADS, 4)
void snn_scan_kernel(const float* __restrict__ x,
                     const float* __restrict__ W1,
                     const float* __restrict__ V,
                     const float* __restrict__ W2,
                     const float* __restrict__ pb1,
                     const float* __restrict__ pb2,
                     const float* __restrict__ pth,
                     float* __restrict__ out)
{
    __shared__ float xsh[2][X_THREADS];     // double-buffered x tile
    __shared__ float s1sh[2][NB * 40];      // double-buffered spk1 staging (pad 40)
    __shared__ float w2sh[NL2 * W2STRIDE];  // W2 rows, padded stride

    const int tid = threadIdx.x;
    const int b0  = blockIdx.x * NB;

    const float beta1 = *pb1;
    const float beta2 = *pb2;
    const float thr   = *pth;

    // ---- one-time shared init ----
    for (int i = tid; i < NL2 * W2STRIDE; i += NTHREADS) {
        int k = i / W2STRIDE;
        int j = i - k * W2STRIDE;
        w2sh[i] = (j < NL1) ? W2[k * NL1 + j] : 0.0f;
    }
    if (tid < 16) {  // zero the padding lanes of both s1 buffers
        int p = tid >> 3, b = (tid >> 1) & 3, c = tid & 1;
        s1sh[p][b * 40 + 38 + c] = 0.0f;
    }

    const bool isX  = (tid < X_THREADS);
    const bool isL1 = (tid < L1_THREADS);
    const bool isL2 = (tid >= L2_BASE) && (tid < L2_BASE + L2_THREADS);

    // ---- layer 1 per-thread state ----
    float w1r[NIN];
    float vj = 0.0f, mem1 = 0.0f, spk1 = 0.0f;
    int s1idx = 0, xoff = 0;
    float *pS1 = out, *pM1 = out;
    if (isL1) {
        int bl = tid / NL1;
        int j  = tid - bl * NL1;
        #pragma unroll
        for (int i = 0; i < NIN; ++i) w1r[i] = W1[j * NIN + i];
        vj    = V[j];
        s1idx = bl * 40 + j;
        xoff  = bl * NIN;
        size_t o = (size_t)(b0 + bl) * NL1 + j;
        pS1 = out + o;
        pM1 = out + (size_t)T_STEPS * BATCH * NL1 + o;
    }

    // ---- layer 2 per-thread state (weights live in shared) ----
    float mem2 = 0.0f;
    int s2off = 0;
    const float4* w2v = (const float4*)w2sh;
    float *pS2 = out, *pM2 = out;
    if (isL2) {
        int t2 = tid - L2_BASE;
        int bl = t2 / NL2;
        int k  = t2 - bl * NL2;
        s2off = bl * 40;
        w2v   = (const float4*)&w2sh[k * W2STRIDE];
        size_t o = (size_t)(b0 + bl) * NL2 + k;
        pS2 = out + (size_t)2 * T_STEPS * BATCH * NL1 + o;
        pM2 = out + (size_t)2 * T_STEPS * BATCH * NL1
                  + (size_t)T_STEPS * BATCH * NL2 + o;
    }

    // ---- x prefetch pipeline: stage t=0 into xsh[0], hold t=1 in xn ----
    const size_t stepx = (size_t)BATCH * NIN;
    const size_t step1 = (size_t)BATCH * NL1;
    const size_t step2 = (size_t)BATCH * NL2;
    const float* xp = x + (size_t)b0 * NIN + tid;  // valid layout for tid < 48
    float xn = 0.0f;
    if (isX) {
        xsh[0][tid] = xp[0];
        xn = xp[stepx];
        xp += 2 * stepx;
    }
    __syncthreads();

    // One barrier per step. Iteration t:
    //   pre-BAR : L1 reads xsh[P], writes s1sh[P] + STG; X stages xsh[P^1] for t+1
    //   BAR
    //   post-BAR: L2 reads s1sh[P] + STG
    // All buffer reuse pairs are separated by exactly one barrier.
#define SNN_STEP(P, TCUR)                                                     \
    {                                                                          \
        if (isL1) {                                                            \
            const float4* xv = reinterpret_cast<const float4*>(&xsh[P][xoff]); \
            float4 a = xv[0], b = xv[1], c = xv[2];                            \
            float cur = a.x * w1r[0];                                          \
            cur = fmaf(a.y, w1r[1], cur);                                      \
            cur = fmaf(a.z, w1r[2], cur);                                      \
            cur = fmaf(a.w, w1r[3], cur);                                      \
            cur = fmaf(b.x, w1r[4], cur);                                      \
            cur = fmaf(b.y, w1r[5], cur);                                      \
            cur = fmaf(b.z, w1r[6], cur);                                      \
            cur = fmaf(b.w, w1r[7], cur);                                      \
            cur = fmaf(c.x, w1r[8], cur);                                      \
            cur = fmaf(c.y, w1r[9], cur);                                      \
            cur = fmaf(c.z, w1r[10], cur);                                     \
            cur = fmaf(c.w, w1r[11], cur);                                     \
            float m = fmaf(beta1, mem1, cur);                                  \
            m = fmaf(vj, spk1, m);                                             \
            float s = (m > thr) ? 1.0f : 0.0f;                                 \
            m = fmaf(-s, thr, m);                                              \
            mem1 = m; spk1 = s;                                                \
            s1sh[P][s1idx] = s;                                                \
            *pS1 = s; *pM1 = m;                                                \
            pS1 += step1; pM1 += step1;                                        \
        }                                                                      \
        if (isX) {                                                             \
            xsh[(P) ^ 1][tid] = xn;                                            \
            if ((TCUR) + 2 < T_STEPS) { xn = *xp; xp += stepx; }               \
        }                                                                      \
        __syncthreads();                                                       \
        if (isL2) {                                                            \
            const float4* sv = reinterpret_cast<const float4*>(&s1sh[P][s2off]);\
            float acc0 = 0.0f, acc1 = 0.0f, acc2 = 0.0f, acc3 = 0.0f;          \
            _Pragma("unroll")                                                  \
            for (int q = 0; q < 10; ++q) {                                     \
                float4 s4 = sv[q];                                             \
                float4 w4 = w2v[q];                                            \
                acc0 = fmaf(s4.x, w4.x, acc0);                                 \
                acc1 = fmaf(s4.y, w4.y, acc1);                                 \
                acc2 = fmaf(s4.z, w4.z, acc2);                                 \
                acc3 = fmaf(s4.w, w4.w, acc3);                                 \
            }                                                                  \
            float cur2 = (acc0 + acc1) + (acc2 + acc3);                        \
            float m = fmaf(beta2, mem2, cur2);                                 \
            float s = (m > thr) ? 1.0f : 0.0f;                                 \
            m = fmaf(-s, thr, m);                                              \
            mem2 = m;                                                          \
            *pS2 = s; *pM2 = m;                                                \
            pS2 += step2; pM2 += step2;                                        \
        }                                                                      \
    }

    #pragma unroll 1
    for (int t = 0; t < T_STEPS; t += 2) {
        SNN_STEP(0, t)
        SNN_STEP(1, t + 1)
    }
#undef SNN_STEP
}

extern "C" void kernel_launch(void* const* d_in, const int* in_sizes, int n_in,
                              void* d_out, int out_size)
{
    const float* x   = (const float*)d_in[0];
    const float* W1  = (const float*)d_in[1];
    const float* V   = (const float*)d_in[2];
    const float* W2  = (const float*)d_in[3];
    const float* b1  = (const float*)d_in[4];
    const float* b2  = (const float*)d_in[5];
    const float* th  = (const float*)d_in[6];
    float* out = (float*)d_out;

    dim3 grid(BATCH / NB);   // 512 blocks; 4 blocks/SM resident -> single wave
    dim3 block(NTHREADS);
    snn_scan_kernel<<<grid, block>>>(x, W1, V, W2, b1, b2, th, out);
}

// round 6
// speedup vs baseline: 1.0527x; 1.0527x over previous
#include <cuda_runtime.h>

// SimpleSNN: T=500 sequential steps, B=2048, 12 -> 38 (RLeaky) -> 7 (Leaky)
// Outputs flat: spk1[T,B,38], mem1[T,B,38], spk2[T,B,7], mem2[T,B,7]
//
// One __syncthreads per step. L2 is software-pipelined one step behind L1:
// phase t runs L1(t) and L2(t-1) concurrently on disjoint warps/buffers.
// L1/L2 reduction orders are bit-identical to the round-3 passing kernel.

#define T_STEPS  500
#define BATCH    2048
#define NIN      12
#define NL1      38
#define NL2      7
#define NB       4              // batch elements per block
#define NTHREADS 192
#define L1_T     (NB*NL1)       // 152
#define L2_BASE  160            // L2 warp starts at warp boundary
#define L2_T     (NB*NL2)       // 28
#define X_T      (NB*NIN)       // 48
#define W2STRIDE 44             // padded W2 row stride (conflict-free broadcast)

__global__ __launch_bounds__(NTHREADS, 4)
void snn_scan_kernel(const float* __restrict__ x,
                     const float* __restrict__ W1,
                     const float* __restrict__ V,
                     const float* __restrict__ W2,
                     const float* __restrict__ pb1,
                     const float* __restrict__ pb2,
                     const float* __restrict__ pth,
                     float* __restrict__ out)
{
    __shared__ float xsh[2][X_T];          // double-buffered x tile
    __shared__ float s1sh[2][NB * 40];     // double-buffered spk1 (padded to 40)
    __shared__ float w2sh[NL2 * W2STRIDE]; // W2 rows, padded stride

    const int tid = threadIdx.x;
    const int b0  = blockIdx.x * NB;

    const float beta1 = *pb1;
    const float beta2 = *pb2;
    const float thr   = *pth;

    const size_t stepx = (size_t)BATCH * NIN;
    const size_t step1 = (size_t)BATCH * NL1;
    const size_t step2 = (size_t)BATCH * NL2;

    // ---- one-time shared init ----
    for (int i = tid; i < NL2 * W2STRIDE; i += NTHREADS) {
        int k = i / W2STRIDE;
        int j = i - k * W2STRIDE;
        w2sh[i] = (j < NL1) ? W2[k * NL1 + j] : 0.0f;
    }
    if (tid < 16) {  // zero padding lanes of both s1 parities
        int par = tid >> 3, r = tid & 7;
        s1sh[par][(r >> 1) * 40 + 38 + (r & 1)] = 0.0f;
    }

    const bool isL1 = (tid < L1_T);
    const bool isX  = (tid < X_T);
    const bool isL2 = (tid >= L2_BASE) && (tid < L2_BASE + L2_T);

    // ---- layer 1 per-thread state ----
    float w1r[NIN];
    float vj = 0.f, mem1 = 0.f, spk1 = 0.f;
    int xoff = 0, s1idx = 0;
    float *pS1 = out, *pM1 = out;
    if (isL1) {
        int bl = tid / NL1, j = tid - bl * NL1;
        #pragma unroll
        for (int i = 0; i < NIN; ++i) w1r[i] = W1[j * NIN + i];
        vj    = V[j];
        xoff  = bl * NIN;
        s1idx = bl * 40 + j;
        size_t o = (size_t)(b0 + bl) * NL1 + j;
        pS1 = out + o;
        pM1 = out + (size_t)T_STEPS * BATCH * NL1 + o;
    }

    // ---- layer 2 per-thread state (W2 in shared) ----
    float mem2 = 0.f;
    int s2off = 0;
    const float4* w2v = (const float4*)w2sh;
    float *pS2 = out, *pM2 = out;
    if (isL2) {
        int t2 = tid - L2_BASE;
        int bl = t2 / NL2, k = t2 - bl * NL2;
        s2off = bl * 40;
        w2v   = (const float4*)&w2sh[k * W2STRIDE];
        size_t o = (size_t)(b0 + bl) * NL2 + k;
        pS2 = out + (size_t)2 * T_STEPS * BATCH * NL1 + o;
        pM2 = pS2 + (size_t)T_STEPS * BATCH * NL2;
    }

    // ---- x pipeline: xsh[0] <- x[0]; xn <- x[1] ----
    const float* xp = x + (size_t)b0 * NIN + tid;   // valid for tid < 48
    float xn = 0.f;
    if (isX) {
        xsh[0][tid] = xp[0];
        xn = xp[stepx];
        xp += 2 * stepx;
    }
    __syncthreads();

    // L1 body for step TC (parity P), then x staging for TC+1.
    // Serial fmaf chain — EXACT order of the round-3 passing kernel.
#define L1BODY(P, TC)                                                          \
        if (isL1) {                                                            \
            const float4* xv = (const float4*)&xsh[P][xoff];                   \
            float4 a = xv[0], b = xv[1], c = xv[2];                            \
            float cur = a.x * w1r[0];                                          \
            cur = fmaf(a.y, w1r[1], cur);                                      \
            cur = fmaf(a.z, w1r[2], cur);                                      \
            cur = fmaf(a.w, w1r[3], cur);                                      \
            cur = fmaf(b.x, w1r[4], cur);                                      \
            cur = fmaf(b.y, w1r[5], cur);                                      \
            cur = fmaf(b.z, w1r[6], cur);                                      \
            cur = fmaf(b.w, w1r[7], cur);                                      \
            cur = fmaf(c.x, w1r[8], cur);                                      \
            cur = fmaf(c.y, w1r[9], cur);                                      \
            cur = fmaf(c.z, w1r[10], cur);                                     \
            cur = fmaf(c.w, w1r[11], cur);                                     \
            float m = fmaf(beta1, mem1, cur);                                  \
            m = fmaf(vj, spk1, m);                                             \
            float s = (m > thr) ? 1.0f : 0.0f;                                 \
            m = fmaf(-s, thr, m);                                              \
            mem1 = m; spk1 = s;                                                \
            s1sh[P][s1idx] = s;                                                \
            *pS1 = s; *pM1 = m;                                                \
            pS1 += step1; pM1 += step1;                                        \
        }                                                                      \
        if (isX) {                                                             \
            xsh[(P) ^ 1][tid] = xn;                                            \
            if ((TC) + 2 < T_STEPS) { xn = *xp; xp += stepx; }                 \
        }

    // L2 body consuming spk1 of parity PP — same accumulation order as round 3.
#define L2BODY(PP)                                                             \
        if (isL2) {                                                            \
            const float4* sv = (const float4*)&s1sh[PP][s2off];                \
            float acc0 = 0.0f, acc1 = 0.0f, acc2 = 0.0f, acc3 = 0.0f;          \
            _Pragma("unroll")                                                  \
            for (int q = 0; q < 10; ++q) {                                     \
                float4 s4 = sv[q];                                             \
                float4 w4 = w2v[q];                                            \
                acc0 = fmaf(s4.x, w4.x, acc0);                                 \
                acc1 = fmaf(s4.y, w4.y, acc1);                                 \
                acc2 = fmaf(s4.z, w4.z, acc2);                                 \
                acc3 = fmaf(s4.w, w4.w, acc3);                                 \
            }                                                                  \
            float cur2 = (acc0 + acc1) + (acc2 + acc3);                        \
            float m2 = fmaf(beta2, mem2, cur2);                                \
            float s2 = (m2 > thr) ? 1.0f : 0.0f;                               \
            m2 = fmaf(-s2, thr, m2);                                           \
            mem2 = m2;                                                         \
            *pS2 = s2; *pM2 = m2;                                              \
            pS2 += step2; pM2 += step2;                                        \
        }

    // step 0: L1 only (no L2 yet)
    L1BODY(0, 0)
    __syncthreads();

    // steps 1..498 (pairs): phase t runs L1(t) and L2(t-1) concurrently
    #pragma unroll 1
    for (int t = 1; t < T_STEPS - 1; t += 2) {
        L1BODY(1, t)
        L2BODY(0)
        __syncthreads();
        L1BODY(0, t + 1)
        L2BODY(1)
        __syncthreads();
    }

    // step 499: L1(499) + L2(498)
    L1BODY(1, 499)
    L2BODY(0)
    __syncthreads();

    // epilogue: L2(499)
    L2BODY(1)

#undef L1BODY
#undef L2BODY
}

extern "C" void kernel_launch(void* const* d_in, const int* in_sizes, int n_in,
                              void* d_out, int out_size)
{
    const float* x   = (const float*)d_in[0];
    const float* W1  = (const float*)d_in[1];
    const float* V   = (const float*)d_in[2];
    const float* W2  = (const float*)d_in[3];
    const float* b1  = (const float*)d_in[4];
    const float* b2  = (const float*)d_in[5];
    const float* th  = (const float*)d_in[6];
    float* out = (float*)d_out;

    dim3 grid(BATCH / NB);   // 512 blocks; 4 blocks/SM -> single wave
    dim3 block(NTHREADS);
    snn_scan_kernel<<<grid, block>>>(x, W1, V, W2, b1, b2, th, out);
}

// round 7
// speedup vs baseline: 1.6336x; 1.5517x over previous
#include <cuda_runtime.h>

// SimpleSNN: T=500 sequential steps, B=2048, 12 -> 38 (RLeaky) -> 7 (Leaky)
// Outputs flat: spk1[T,B,38], mem1[T,B,38], spk2[T,B,7], mem2[T,B,7]
//
// Round-batched pipeline: one __syncthreads per ROUND of 4 steps.
// L1 recurrence is thread-local, so L1 runs 4 steps unsynced into an 8-slot
// spk1 ring; L2 consumes the previous round's 4 slots concurrently.
// Per-step arithmetic order is bit-identical to the passing round-3 kernel.

#define T_STEPS  500
#define BATCH    2048
#define NIN      12
#define NL1      38
#define NL2      7
#define NB       4              // batch elements per block
#define NTHREADS 192
#define L1_T     (NB*NL1)       // 152
#define L2_BASE  160            // L2 warp starts at warp boundary
#define L2_T     (NB*NL2)       // 28
#define X_T      (NB*NIN)       // 48
#define W2STRIDE 44             // padded W2 row stride (conflict-free broadcast)
#define GSTEP    4              // steps per round
#define NSLOT    8              // ring depth (2 rounds)

__global__ __launch_bounds__(NTHREADS, 4)
void snn_scan_kernel(const float* __restrict__ x,
                     const float* __restrict__ W1,
                     const float* __restrict__ V,
                     const float* __restrict__ W2,
                     const float* __restrict__ pb1,
                     const float* __restrict__ pb2,
                     const float* __restrict__ pth,
                     float* __restrict__ out)
{
    __shared__ float xsh[NSLOT][X_T];       // x ring: one slot per step
    __shared__ float s1sh[NSLOT][NB * 40];  // spk1 ring (rows padded to 40)
    __shared__ float w2sh[NL2 * W2STRIDE];  // W2 rows, padded stride

    const int tid = threadIdx.x;
    const int b0  = blockIdx.x * NB;

    const float beta1 = *pb1;
    const float beta2 = *pb2;
    const float thr   = *pth;

    const size_t stepx = (size_t)BATCH * NIN;
    const size_t step1 = (size_t)BATCH * NL1;
    const size_t step2 = (size_t)BATCH * NL2;

    // ---- one-time shared init ----
    for (int i = tid; i < NL2 * W2STRIDE; i += NTHREADS) {
        int k = i / W2STRIDE;
        int j = i - k * W2STRIDE;
        w2sh[i] = (j < NL1) ? W2[k * NL1 + j] : 0.0f;
    }
    // zero the 2 padding lanes of each batch row in all 8 slots (64 writes)
    if (tid < 64) {
        int sl = tid >> 3, r = tid & 7;
        s1sh[sl][(r >> 1) * 40 + 38 + (r & 1)] = 0.0f;
    }

    const bool isL1 = (tid < L1_T);
    const bool isX  = (tid < X_T);
    const bool isL2 = (tid >= L2_BASE) && (tid < L2_BASE + L2_T);

    // ---- layer 1 per-thread state ----
    float w1r[NIN];
    float vj = 0.f, mem1 = 0.f, spk1 = 0.f;
    int xoff = 0, s1idx = 0;
    float *pS1 = out, *pM1 = out;
    if (isL1) {
        int bl = tid / NL1, j = tid - bl * NL1;
        #pragma unroll
        for (int i = 0; i < NIN; ++i) w1r[i] = W1[j * NIN + i];
        vj    = V[j];
        xoff  = bl * NIN;
        s1idx = bl * 40 + j;
        size_t o = (size_t)(b0 + bl) * NL1 + j;
        pS1 = out + o;
        pM1 = out + (size_t)T_STEPS * BATCH * NL1 + o;
    }

    // ---- layer 2 per-thread state (W2 in shared) ----
    float mem2 = 0.f;
    int s2off = 0;
    const float4* w2v = (const float4*)w2sh;
    float *pS2 = out, *pM2 = out;
    if (isL2) {
        int t2 = tid - L2_BASE;
        int bl = t2 / NL2, k = t2 - bl * NL2;
        s2off = bl * 40;
        w2v   = (const float4*)&w2sh[k * W2STRIDE];
        size_t o = (size_t)(b0 + bl) * NL2 + k;
        pS2 = out + (size_t)2 * T_STEPS * BATCH * NL1 + o;
        pM2 = pS2 + (size_t)T_STEPS * BATCH * NL2;
    }

    // ---- x pipeline: stage steps 0-3 into slots 0-3; hold steps 4-7 in regs ----
    const float* xp = x + (size_t)b0 * NIN + tid;   // valid for tid < 48
    float xn0 = 0.f, xn1 = 0.f, xn2 = 0.f, xn3 = 0.f;
    int tpre = 2 * GSTEP;   // next step-base to prefetch (8)
    if (isX) {
        xsh[0][tid] = xp[0];
        xsh[1][tid] = xp[stepx];
        xsh[2][tid] = xp[2 * stepx];
        xsh[3][tid] = xp[3 * stepx];
        xn0 = xp[4 * stepx];
        xn1 = xp[5 * stepx];
        xn2 = xp[6 * stepx];
        xn3 = xp[7 * stepx];
        xp += 8 * stepx;
    }
    __syncthreads();

    // one L1 step from ring slot SLOT (compile-time). Exact round-3 op order.
#define L1STEP(SLOT)                                                           \
        {                                                                      \
            const float4* xv = (const float4*)&xsh[SLOT][xoff];                \
            float4 a = xv[0], b = xv[1], c = xv[2];                            \
            float cur = a.x * w1r[0];                                          \
            cur = fmaf(a.y, w1r[1], cur);                                      \
            cur = fmaf(a.z, w1r[2], cur);                                      \
            cur = fmaf(a.w, w1r[3], cur);                                      \
            cur = fmaf(b.x, w1r[4], cur);                                      \
            cur = fmaf(b.y, w1r[5], cur);                                      \
            cur = fmaf(b.z, w1r[6], cur);                                      \
            cur = fmaf(b.w, w1r[7], cur);                                      \
            cur = fmaf(c.x, w1r[8], cur);                                      \
            cur = fmaf(c.y, w1r[9], cur);                                      \
            cur = fmaf(c.z, w1r[10], cur);                                     \
            cur = fmaf(c.w, w1r[11], cur);                                     \
            float m = fmaf(beta1, mem1, cur);                                  \
            m = fmaf(vj, spk1, m);                                             \
            float s = (m > thr) ? 1.0f : 0.0f;                                 \
            m = fmaf(-s, thr, m);                                              \
            mem1 = m; spk1 = s;                                                \
            s1sh[SLOT][s1idx] = s;                                             \
            *pS1 = s; *pM1 = m;                                                \
            pS1 += step1; pM1 += step1;                                        \
        }

    // one L2 step from ring slot SLOT. Exact round-3 accumulation order.
#define L2STEP(SLOT)                                                           \
        {                                                                      \
            const float4* sv = (const float4*)&s1sh[SLOT][s2off];              \
            float acc0 = 0.0f, acc1 = 0.0f, acc2 = 0.0f, acc3 = 0.0f;          \
            _Pragma("unroll")                                                  \
            for (int q = 0; q < 10; ++q) {                                     \
                float4 s4 = sv[q];                                             \
                float4 w4 = w2v[q];                                            \
                acc0 = fmaf(s4.x, w4.x, acc0);                                 \
                acc1 = fmaf(s4.y, w4.y, acc1);                                 \
                acc2 = fmaf(s4.z, w4.z, acc2);                                 \
                acc3 = fmaf(s4.w, w4.w, acc3);                                 \
            }                                                                  \
            float cur2 = (acc0 + acc1) + (acc2 + acc3);                        \
            float m2 = fmaf(beta2, mem2, cur2);                                \
            float s2 = (m2 > thr) ? 1.0f : 0.0f;                               \
            m2 = fmaf(-s2, thr, m2);                                           \
            mem2 = m2;                                                         \
            *pS2 = s2; *pM2 = m2;                                              \
            pS2 += step2; pM2 += step2;                                        \
        }

    // L1 round at slot base BASE; X stages next round's slots (BASE^4) and
    // prefetches the round after (guarded; T_STEPS % 4 == 0 so all-or-none).
#define L1ROUND(BASE)                                                          \
        if (isL1) {                                                            \
            L1STEP(BASE + 0) L1STEP(BASE + 1) L1STEP(BASE + 2) L1STEP(BASE + 3)\
        }                                                                      \
        if (isX) {                                                             \
            xsh[(BASE ^ 4) + 0][tid] = xn0;                                    \
            xsh[(BASE ^ 4) + 1][tid] = xn1;                                    \
            xsh[(BASE ^ 4) + 2][tid] = xn2;                                    \
            xsh[(BASE ^ 4) + 3][tid] = xn3;                                    \
            if (tpre < T_STEPS) {                                              \
                xn0 = xp[0];                                                   \
                xn1 = xp[stepx];                                               \
                xn2 = xp[2 * stepx];                                           \
                xn3 = xp[3 * stepx];                                           \
                xp += 4 * stepx;                                               \
            }                                                                  \
            tpre += GSTEP;                                                     \
        }

#define L2ROUND(BASE)                                                          \
        if (isL2) {                                                            \
            L2STEP(BASE + 0) L2STEP(BASE + 1) L2STEP(BASE + 2) L2STEP(BASE + 3)\
        }

    // round 0: L1 only
    L1ROUND(0)
    __syncthreads();

    // rounds 1..124: L1 leads, L2 trails one round (62 pairs)
    #pragma unroll 1
    for (int r = 0; r < 62; ++r) {
        L1ROUND(4) L2ROUND(0)
        __syncthreads();
        L1ROUND(0) L2ROUND(4)
        __syncthreads();
    }

    // epilogue: L2 for steps 496-499 (slot base 0)
    L2ROUND(0)

#undef L1STEP
#undef L2STEP
#undef L1ROUND
#undef L2ROUND
}

extern "C" void kernel_launch(void* const* d_in, const int* in_sizes, int n_in,
                              void* d_out, int out_size)
{
    const float* x   = (const float*)d_in[0];
    const float* W1  = (const float*)d_in[1];
    const float* V   = (const float*)d_in[2];
    const float* W2  = (const float*)d_in[3];
    const float* b1  = (const float*)d_in[4];
    const float* b2  = (const float*)d_in[5];
    const float* th  = (const float*)d_in[6];
    float* out = (float*)d_out;

    dim3 grid(BATCH / NB);   // 512 blocks; 4 blocks/SM -> single wave
    dim3 block(NTHREADS);
    snn_scan_kernel<<<grid, block>>>(x, W1, V, W2, b1, b2, th, out);
}